// round 2
// baseline (speedup 1.0000x reference)
#include <cuda_runtime.h>
#include <math.h>

#define NNODES 100000
#define DFEAT  128

// Scratch (allocation-free: static device globals)
__device__ float g_Wh [NNODES * DFEAT];          // W(h)        51.2 MB
__device__ float g_Wth[NNODES * DFEAT];          // W_trans(h)  51.2 MB
__device__ float g_hT [DFEAT * NNODES];          // h transposed [k][m] 51.2 MB
__device__ float g_WT [3 * DFEAT * DFEAT];       // weights transposed [k][o]

// ---------------------------------------------------------------------------
// Transpose h [N,128] -> g_hT [128,N]  (32x32 smem tiles, conflict-free)
// ---------------------------------------------------------------------------
__global__ void transpose_h_kernel(const float* __restrict__ h, int Nn) {
    __shared__ float tile[32][33];
    int m0 = blockIdx.x * 32;
    int k0 = blockIdx.y * 32;
    int tx = threadIdx.x;          // 0..31
    int ty = threadIdx.y;          // 0..7
    #pragma unroll
    for (int i = ty; i < 32; i += 8) {
        int m = m0 + i;
        tile[i][tx] = (m < Nn) ? h[(size_t)m * DFEAT + k0 + tx] : 0.0f;
    }
    __syncthreads();
    #pragma unroll
    for (int i = ty; i < 32; i += 8) {
        int m = m0 + tx;
        if (m < Nn) g_hT[(size_t)(k0 + i) * Nn + m] = tile[tx][i];
    }
}

// ---------------------------------------------------------------------------
// Transpose the three 128x128 weight matrices into g_WT (k-major)
// ---------------------------------------------------------------------------
__global__ void transpose_W_kernel(const float* __restrict__ W0,
                                   const float* __restrict__ W1,
                                   const float* __restrict__ W2) {
    __shared__ float tile[32][33];
    const float* W = (blockIdx.z == 0) ? W0 : (blockIdx.z == 1) ? W1 : W2;
    float* out = g_WT + blockIdx.z * DFEAT * DFEAT;
    int o0 = blockIdx.x * 32;
    int k0 = blockIdx.y * 32;
    int tx = threadIdx.x;
    int ty = threadIdx.y;
    #pragma unroll
    for (int i = ty; i < 32; i += 8)
        tile[i][tx] = W[(o0 + i) * DFEAT + k0 + tx];
    __syncthreads();
    #pragma unroll
    for (int i = ty; i < 32; i += 8)
        out[(k0 + i) * DFEAT + o0 + tx] = tile[tx][i];
}

// ---------------------------------------------------------------------------
// GEMM: out[m][o] = sum_k h[m][k] * W[o][k] + b[o]
// Inputs pre-transposed (k-major). Block = 128 rows x 128 cols, 256 threads,
// 8x8 microtile per thread. blockIdx.y selects which of the 3 projections.
// ---------------------------------------------------------------------------
extern "C" __global__ void __launch_bounds__(256, 1)
gemm_kernel(const float* __restrict__ b0,
            const float* __restrict__ b1,
            const float* __restrict__ b2,
            float* __restrict__ out_self, int Nn) {
    extern __shared__ float smem[];
    float* sH = smem;                 // [128][128]  sH[k*128 + m]
    float* sW = smem + 128 * 128;     // [128][128]  sW[k*128 + o]

    int which = blockIdx.y;
    const float* WT  = g_WT + which * DFEAT * DFEAT;
    const float* bias = (which == 0) ? b0 : (which == 1) ? b1 : b2;
    float* out = (which == 0) ? g_Wh : (which == 1) ? g_Wth : out_self;

    int m0  = blockIdx.x * 128;
    int tid = threadIdx.x;
    int mrem = Nn - m0;               // >= 1

    // Load tiles: both fully coalesced (inputs are k-major already)
    for (int idx = tid; idx < 4096; idx += 256) {
        int k  = idx >> 5;            // 32 float4 per 128-float row
        int m4 = (idx & 31) * 4;
        float4 v;
        if (m4 + 3 < mrem) {
            v = *(const float4*)&g_hT[(size_t)k * Nn + m0 + m4];
        } else {
            float t0 = (m4 + 0 < mrem) ? g_hT[(size_t)k * Nn + m0 + m4 + 0] : 0.f;
            float t1 = (m4 + 1 < mrem) ? g_hT[(size_t)k * Nn + m0 + m4 + 1] : 0.f;
            float t2 = (m4 + 2 < mrem) ? g_hT[(size_t)k * Nn + m0 + m4 + 2] : 0.f;
            float t3 = (m4 + 3 < mrem) ? g_hT[(size_t)k * Nn + m0 + m4 + 3] : 0.f;
            v = make_float4(t0, t1, t2, t3);
        }
        *(float4*)&sH[k * 128 + m4] = v;
        *(float4*)&sW[idx * 4] = *(const float4*)&WT[idx * 4];
    }
    __syncthreads();

    int tx = tid & 15;                // output-col group
    int ty = tid >> 4;                // output-row group

    float acc[8][8];
    #pragma unroll
    for (int i = 0; i < 8; i++)
        #pragma unroll
        for (int j = 0; j < 8; j++) acc[i][j] = 0.0f;

    #pragma unroll 4
    for (int k = 0; k < 128; k++) {
        float4 a0 = *(const float4*)&sH[k * 128 + ty * 8];
        float4 a1 = *(const float4*)&sH[k * 128 + ty * 8 + 4];
        float4 w0 = *(const float4*)&sW[k * 128 + tx * 8];
        float4 w1 = *(const float4*)&sW[k * 128 + tx * 8 + 4];
        float a[8] = {a0.x, a0.y, a0.z, a0.w, a1.x, a1.y, a1.z, a1.w};
        float b[8] = {w0.x, w0.y, w0.z, w0.w, w1.x, w1.y, w1.z, w1.w};
        #pragma unroll
        for (int i = 0; i < 8; i++)
            #pragma unroll
            for (int j = 0; j < 8; j++)
                acc[i][j] += a[i] * b[j];
    }

    // Epilogue: add bias, store
    float4 bv0 = *(const float4*)&bias[tx * 8];
    float4 bv1 = *(const float4*)&bias[tx * 8 + 4];
    float br[8] = {bv0.x, bv0.y, bv0.z, bv0.w, bv1.x, bv1.y, bv1.z, bv1.w};

    #pragma unroll
    for (int i = 0; i < 8; i++) {
        int m = m0 + ty * 8 + i;
        if (m < Nn) {
            float4 r0 = make_float4(acc[i][0] + br[0], acc[i][1] + br[1],
                                    acc[i][2] + br[2], acc[i][3] + br[3]);
            float4 r1 = make_float4(acc[i][4] + br[4], acc[i][5] + br[5],
                                    acc[i][6] + br[6], acc[i][7] + br[7]);
            *(float4*)&out[(size_t)m * DFEAT + tx * 8]     = r0;
            *(float4*)&out[(size_t)m * DFEAT + tx * 8 + 4] = r1;
        }
    }
}

// ---------------------------------------------------------------------------
// Edge aggregation: one warp per edge.
//   acc[rows[e]] += Wh[cols[e]]   and   acc[cols[e]] += Wth[rows[e]]
// ---------------------------------------------------------------------------
__global__ void edge_kernel(const int* __restrict__ rows,
                            const int* __restrict__ cols,
                            float* __restrict__ acc, int E) {
    int warp = (blockIdx.x * blockDim.x + threadIdx.x) >> 5;
    int lane = threadIdx.x & 31;
    if (warp >= E) return;
    int r = rows[warp];
    int c = cols[warp];

    float4 v1 = *(const float4*)&g_Wh [(size_t)c * DFEAT + lane * 4];
    float4 v2 = *(const float4*)&g_Wth[(size_t)r * DFEAT + lane * 4];

    float* d1 = &acc[(size_t)r * DFEAT + lane * 4];
    atomicAdd(d1 + 0, v1.x);
    atomicAdd(d1 + 1, v1.y);
    atomicAdd(d1 + 2, v1.z);
    atomicAdd(d1 + 3, v1.w);

    float* d2 = &acc[(size_t)c * DFEAT + lane * 4];
    atomicAdd(d2 + 0, v2.x);
    atomicAdd(d2 + 1, v2.y);
    atomicAdd(d2 + 2, v2.z);
    atomicAdd(d2 + 3, v2.w);
}

// ---------------------------------------------------------------------------
// Exact GELU (erf-based), in place, float4-vectorized
// ---------------------------------------------------------------------------
__global__ void gelu_kernel(float* __restrict__ x, int n4) {
    int i = blockIdx.x * blockDim.x + threadIdx.x;
    if (i >= n4) return;
    float4 v = ((float4*)x)[i];
    const float k = 0.70710678118654752440f;  // 1/sqrt(2)
    v.x = 0.5f * v.x * (1.0f + erff(v.x * k));
    v.y = 0.5f * v.y * (1.0f + erff(v.y * k));
    v.z = 0.5f * v.z * (1.0f + erff(v.z * k));
    v.w = 0.5f * v.w * (1.0f + erff(v.w * k));
    ((float4*)x)[i] = v;
}

// ---------------------------------------------------------------------------
extern "C" void kernel_launch(void* const* d_in, const int* in_sizes, int n_in,
                              void* d_out, int out_size) {
    const float* h    = (const float*)d_in[0];
    const float* W_w  = (const float*)d_in[1];
    const float* W_b  = (const float*)d_in[2];
    const float* Wt_w = (const float*)d_in[3];
    const float* Wt_b = (const float*)d_in[4];
    const float* Ws_w = (const float*)d_in[5];
    const float* Ws_b = (const float*)d_in[6];
    const int*   rows = (const int*)d_in[7];
    const int*   cols = (const int*)d_in[8];
    int Nn = in_sizes[0] / DFEAT;
    int E  = in_sizes[7];
    float* out = (float*)d_out;

    // 1. Transposes (h -> k-major, W -> k-major)
    transpose_h_kernel<<<dim3((Nn + 31) / 32, DFEAT / 32), dim3(32, 8)>>>(h, Nn);
    transpose_W_kernel<<<dim3(4, 4, 3), dim3(32, 8)>>>(W_w, Wt_w, Ws_w);

    // 2. Three projections (y=2 writes W_self(h) straight into d_out as the
    //    accumulator; every element written, so the 0xAA poison is cleared)
    cudaFuncSetAttribute(gemm_kernel,
                         cudaFuncAttributeMaxDynamicSharedMemorySize, 131072);
    gemm_kernel<<<dim3((Nn + 127) / 128, 3), 256, 131072>>>(W_b, Wt_b, Ws_b,
                                                            out, Nn);

    // 3. Bidirectional edge aggregation (atomics into d_out)
    int warps_per_block = 256 / 32;
    int eblocks = (E + warps_per_block - 1) / warps_per_block;
    edge_kernel<<<eblocks, 256>>>(rows, cols, out, E);

    // 4. Exact GELU in place
    int n4 = Nn * DFEAT / 4;
    gelu_kernel<<<(n4 + 255) / 256, 256>>>(out, n4);
}

// round 3
// speedup vs baseline: 1.8496x; 1.8496x over previous
#include <cuda_runtime.h>
#include <math.h>

#define NNODES 100000
#define DFEAT  128

// Scratch (allocation-free: static device globals)
__device__ float g_Wh [NNODES * DFEAT];          // W(h)        51.2 MB
__device__ float g_Wth[NNODES * DFEAT];          // W_trans(h)  51.2 MB
__device__ float g_hT [DFEAT * NNODES];          // h transposed [k][m] 51.2 MB
__device__ float g_WT [3 * DFEAT * DFEAT];       // weights transposed [k][o]

// ---------------------------------------------------------------------------
// Transpose h [N,128] -> g_hT [128,N]  (32x32 smem tiles, conflict-free)
// ---------------------------------------------------------------------------
__global__ void transpose_h_kernel(const float* __restrict__ h, int Nn) {
    __shared__ float tile[32][33];
    int m0 = blockIdx.x * 32;
    int k0 = blockIdx.y * 32;
    int tx = threadIdx.x;          // 0..31
    int ty = threadIdx.y;          // 0..7
    #pragma unroll
    for (int i = ty; i < 32; i += 8) {
        int m = m0 + i;
        tile[i][tx] = (m < Nn) ? h[(size_t)m * DFEAT + k0 + tx] : 0.0f;
    }
    __syncthreads();
    #pragma unroll
    for (int i = ty; i < 32; i += 8) {
        int m = m0 + tx;
        if (m < Nn) g_hT[(size_t)(k0 + i) * Nn + m] = tile[tx][i];
    }
}

// ---------------------------------------------------------------------------
// Transpose the three 128x128 weight matrices into g_WT (k-major)
// ---------------------------------------------------------------------------
__global__ void transpose_W_kernel(const float* __restrict__ W0,
                                   const float* __restrict__ W1,
                                   const float* __restrict__ W2) {
    __shared__ float tile[32][33];
    const float* W = (blockIdx.z == 0) ? W0 : (blockIdx.z == 1) ? W1 : W2;
    float* out = g_WT + blockIdx.z * DFEAT * DFEAT;
    int o0 = blockIdx.x * 32;
    int k0 = blockIdx.y * 32;
    int tx = threadIdx.x;
    int ty = threadIdx.y;
    #pragma unroll
    for (int i = ty; i < 32; i += 8)
        tile[i][tx] = W[(o0 + i) * DFEAT + k0 + tx];
    __syncthreads();
    #pragma unroll
    for (int i = ty; i < 32; i += 8)
        out[(k0 + i) * DFEAT + o0 + tx] = tile[tx][i];
}

// ---------------------------------------------------------------------------
// GEMM: out[m][o] = sum_k h[m][k] * W[o][k] + b[o]
// Inputs pre-transposed (k-major). Block = 128 rows x 128 cols, 256 threads,
// 8x8 microtile per thread. blockIdx.y selects which of the 3 projections.
// ---------------------------------------------------------------------------
extern "C" __global__ void __launch_bounds__(256, 1)
gemm_kernel(const float* __restrict__ b0,
            const float* __restrict__ b1,
            const float* __restrict__ b2,
            float* __restrict__ out_self, int Nn) {
    extern __shared__ float smem[];
    float* sH = smem;                 // [128][128]  sH[k*128 + m]
    float* sW = smem + 128 * 128;     // [128][128]  sW[k*128 + o]

    int which = blockIdx.y;
    const float* WT  = g_WT + which * DFEAT * DFEAT;
    const float* bias = (which == 0) ? b0 : (which == 1) ? b1 : b2;
    float* out = (which == 0) ? g_Wh : (which == 1) ? g_Wth : out_self;

    int m0  = blockIdx.x * 128;
    int tid = threadIdx.x;
    int mrem = Nn - m0;               // >= 1

    // Load tiles: both fully coalesced (inputs are k-major already)
    for (int idx = tid; idx < 4096; idx += 256) {
        int k  = idx >> 5;            // 32 float4 per 128-float row
        int m4 = (idx & 31) * 4;
        float4 v;
        if (m4 + 3 < mrem) {
            v = *(const float4*)&g_hT[(size_t)k * Nn + m0 + m4];
        } else {
            float t0 = (m4 + 0 < mrem) ? g_hT[(size_t)k * Nn + m0 + m4 + 0] : 0.f;
            float t1 = (m4 + 1 < mrem) ? g_hT[(size_t)k * Nn + m0 + m4 + 1] : 0.f;
            float t2 = (m4 + 2 < mrem) ? g_hT[(size_t)k * Nn + m0 + m4 + 2] : 0.f;
            float t3 = (m4 + 3 < mrem) ? g_hT[(size_t)k * Nn + m0 + m4 + 3] : 0.f;
            v = make_float4(t0, t1, t2, t3);
        }
        *(float4*)&sH[k * 128 + m4] = v;
        *(float4*)&sW[idx * 4] = *(const float4*)&WT[idx * 4];
    }
    __syncthreads();

    int tx = tid & 15;                // output-col group
    int ty = tid >> 4;                // output-row group

    float acc[8][8];
    #pragma unroll
    for (int i = 0; i < 8; i++)
        #pragma unroll
        for (int j = 0; j < 8; j++) acc[i][j] = 0.0f;

    #pragma unroll 4
    for (int k = 0; k < 128; k++) {
        float4 a0 = *(const float4*)&sH[k * 128 + ty * 8];
        float4 a1 = *(const float4*)&sH[k * 128 + ty * 8 + 4];
        float4 w0 = *(const float4*)&sW[k * 128 + tx * 8];
        float4 w1 = *(const float4*)&sW[k * 128 + tx * 8 + 4];
        float a[8] = {a0.x, a0.y, a0.z, a0.w, a1.x, a1.y, a1.z, a1.w};
        float b[8] = {w0.x, w0.y, w0.z, w0.w, w1.x, w1.y, w1.z, w1.w};
        #pragma unroll
        for (int i = 0; i < 8; i++)
            #pragma unroll
            for (int j = 0; j < 8; j++)
                acc[i][j] += a[i] * b[j];
    }

    // Epilogue: add bias, store
    float4 bv0 = *(const float4*)&bias[tx * 8];
    float4 bv1 = *(const float4*)&bias[tx * 8 + 4];
    float br[8] = {bv0.x, bv0.y, bv0.z, bv0.w, bv1.x, bv1.y, bv1.z, bv1.w};

    #pragma unroll
    for (int i = 0; i < 8; i++) {
        int m = m0 + ty * 8 + i;
        if (m < Nn) {
            float4 r0 = make_float4(acc[i][0] + br[0], acc[i][1] + br[1],
                                    acc[i][2] + br[2], acc[i][3] + br[3]);
            float4 r1 = make_float4(acc[i][4] + br[4], acc[i][5] + br[5],
                                    acc[i][6] + br[6], acc[i][7] + br[7]);
            *(float4*)&out[(size_t)m * DFEAT + tx * 8]     = r0;
            *(float4*)&out[(size_t)m * DFEAT + tx * 8 + 4] = r1;
        }
    }
}

// ---------------------------------------------------------------------------
// Vectorized global reduction: one REDG.128 instead of 4 scalar REDG.F32
// ---------------------------------------------------------------------------
__device__ __forceinline__ void red_add_v4(float* ptr, float4 v) {
    asm volatile("red.global.add.v4.f32 [%0], {%1, %2, %3, %4};"
                 :: "l"(ptr), "f"(v.x), "f"(v.y), "f"(v.z), "f"(v.w)
                 : "memory");
}

// ---------------------------------------------------------------------------
// Edge aggregation: one warp per edge.
//   acc[rows[e]] += Wh[cols[e]]   and   acc[cols[e]] += Wth[rows[e]]
// ---------------------------------------------------------------------------
__global__ void edge_kernel(const int* __restrict__ rows,
                            const int* __restrict__ cols,
                            float* __restrict__ acc, int E) {
    int warp = (blockIdx.x * blockDim.x + threadIdx.x) >> 5;
    int lane = threadIdx.x & 31;
    if (warp >= E) return;
    int r = rows[warp];
    int c = cols[warp];

    float4 v1 = *(const float4*)&g_Wh [(size_t)c * DFEAT + lane * 4];
    float4 v2 = *(const float4*)&g_Wth[(size_t)r * DFEAT + lane * 4];

    red_add_v4(&acc[(size_t)r * DFEAT + lane * 4], v1);
    red_add_v4(&acc[(size_t)c * DFEAT + lane * 4], v2);
}

// ---------------------------------------------------------------------------
// Exact GELU (erf-based), in place, float4-vectorized
// ---------------------------------------------------------------------------
__global__ void gelu_kernel(float* __restrict__ x, int n4) {
    int i = blockIdx.x * blockDim.x + threadIdx.x;
    if (i >= n4) return;
    float4 v = ((float4*)x)[i];
    const float k = 0.70710678118654752440f;  // 1/sqrt(2)
    v.x = 0.5f * v.x * (1.0f + erff(v.x * k));
    v.y = 0.5f * v.y * (1.0f + erff(v.y * k));
    v.z = 0.5f * v.z * (1.0f + erff(v.z * k));
    v.w = 0.5f * v.w * (1.0f + erff(v.w * k));
    ((float4*)x)[i] = v;
}

// ---------------------------------------------------------------------------
extern "C" void kernel_launch(void* const* d_in, const int* in_sizes, int n_in,
                              void* d_out, int out_size) {
    const float* h    = (const float*)d_in[0];
    const float* W_w  = (const float*)d_in[1];
    const float* W_b  = (const float*)d_in[2];
    const float* Wt_w = (const float*)d_in[3];
    const float* Wt_b = (const float*)d_in[4];
    const float* Ws_w = (const float*)d_in[5];
    const float* Ws_b = (const float*)d_in[6];
    const int*   rows = (const int*)d_in[7];
    const int*   cols = (const int*)d_in[8];
    int Nn = in_sizes[0] / DFEAT;
    int E  = in_sizes[7];
    float* out = (float*)d_out;

    // 1. Transposes (h -> k-major, W -> k-major)
    transpose_h_kernel<<<dim3((Nn + 31) / 32, DFEAT / 32), dim3(32, 8)>>>(h, Nn);
    transpose_W_kernel<<<dim3(4, 4, 3), dim3(32, 8)>>>(W_w, Wt_w, Ws_w);

    // 2. Three projections (y=2 writes W_self(h) straight into d_out as the
    //    accumulator; every element written, so the 0xAA poison is cleared)
    cudaFuncSetAttribute(gemm_kernel,
                         cudaFuncAttributeMaxDynamicSharedMemorySize, 131072);
    gemm_kernel<<<dim3((Nn + 127) / 128, 3), 256, 131072>>>(W_b, Wt_b, Ws_b,
                                                            out, Nn);

    // 3. Bidirectional edge aggregation (vectorized reds into d_out)
    int warps_per_block = 256 / 32;
    int eblocks = (E + warps_per_block - 1) / warps_per_block;
    edge_kernel<<<eblocks, 256>>>(rows, cols, out, E);

    // 4. Exact GELU in place
    int n4 = Nn * DFEAT / 4;
    gelu_kernel<<<(n4 + 255) / 256, 256>>>(out, n4);
}

// round 7
// speedup vs baseline: 2.6249x; 1.4191x over previous
#include <cuda_runtime.h>
#include <cstdint>
#include <math.h>

#define NNODES 100000
#define DFEAT  128

// Scratch (allocation-free device globals)
__device__ float g_aggA[NNODES * DFEAT];   // (A  h)   51.2 MB
__device__ float g_aggT[NNODES * DFEAT];   // (A^T h)  51.2 MB
__device__ float g_deg [NNODES + 32];      // row degree  (A 1)
__device__ float g_degT[NNODES + 32];      // col degree  (A^T 1)

// ---------------------------------------------------------------------------
// PTX helpers (base-target only: ldmatrix + mma.sync, no tcgen05)
// ---------------------------------------------------------------------------
__device__ __forceinline__ uint32_t smem_u32(const void* p) {
    uint32_t a;
    asm("{ .reg .u64 t; cvta.to.shared.u64 t, %1; cvt.u32.u64 %0, t; }"
        : "=r"(a) : "l"(p));
    return a;
}

__device__ __forceinline__ uint32_t f32_to_tf32(float f) {
    uint32_t r;
    asm("cvt.rna.tf32.f32 %0, %1;" : "=r"(r) : "f"(f));
    return r;
}

__device__ __forceinline__ void ldsm_x4(uint32_t& r0, uint32_t& r1,
                                        uint32_t& r2, uint32_t& r3,
                                        uint32_t addr) {
    asm volatile("ldmatrix.sync.aligned.m8n8.x4.shared.b16 {%0,%1,%2,%3}, [%4];"
                 : "=r"(r0), "=r"(r1), "=r"(r2), "=r"(r3) : "r"(addr));
}

__device__ __forceinline__ void mma_tf32(float* d, const uint32_t* a,
                                         const uint32_t* b) {
    asm volatile(
        "mma.sync.aligned.m16n8k8.row.col.f32.tf32.tf32.f32 "
        "{%0,%1,%2,%3}, {%4,%5,%6,%7}, {%8,%9}, {%0,%1,%2,%3};"
        : "+f"(d[0]), "+f"(d[1]), "+f"(d[2]), "+f"(d[3])
        : "r"(a[0]), "r"(a[1]), "r"(a[2]), "r"(a[3]), "r"(b[0]), "r"(b[1]));
}

#define SWZ(off) ((off) ^ (((off) >> 3) & 0x70))

// ---------------------------------------------------------------------------
// Zero all accumulators (no pointer args -> no cudaGetSymbolAddress needed)
// ---------------------------------------------------------------------------
__global__ void zero_kernel(int n4each, int nd4) {
    int i = blockIdx.x * blockDim.x + threadIdx.x;
    float4 z = make_float4(0.f, 0.f, 0.f, 0.f);
    if (i < n4each)                 ((float4*)g_aggA)[i] = z;
    else if (i < 2 * n4each)        ((float4*)g_aggT)[i - n4each] = z;
    else if (i < 2 * n4each + nd4)  ((float4*)g_deg )[i - 2 * n4each] = z;
    else if (i < 2 * n4each + 2 * nd4) ((float4*)g_degT)[i - 2 * n4each - nd4] = z;
}

// ---------------------------------------------------------------------------
// Edge aggregation in h-space: one warp per edge.
//   aggA[r] += h[c];  aggT[c] += h[r];  deg[r]+=1; degT[c]+=1
// ---------------------------------------------------------------------------
__device__ __forceinline__ void red_add_v4(float* ptr, float4 v) {
    asm volatile("red.global.add.v4.f32 [%0], {%1, %2, %3, %4};"
                 :: "l"(ptr), "f"(v.x), "f"(v.y), "f"(v.z), "f"(v.w) : "memory");
}
__device__ __forceinline__ void red_add_f32(float* ptr, float v) {
    asm volatile("red.global.add.f32 [%0], %1;" :: "l"(ptr), "f"(v) : "memory");
}

__global__ void edge_kernel(const int* __restrict__ rows,
                            const int* __restrict__ cols,
                            const float* __restrict__ h, int E) {
    int e    = (blockIdx.x * blockDim.x + threadIdx.x) >> 5;
    int lane = threadIdx.x & 31;
    if (e >= E) return;
    int r = rows[e];
    int c = cols[e];

    float4 vc = *(const float4*)&h[(size_t)c * DFEAT + lane * 4];
    float4 vr = *(const float4*)&h[(size_t)r * DFEAT + lane * 4];

    red_add_v4(&g_aggA[(size_t)r * DFEAT + lane * 4], vc);
    red_add_v4(&g_aggT[(size_t)c * DFEAT + lane * 4], vr);
    if (lane == 0) {
        red_add_f32(&g_deg[r],  1.0f);
        red_add_f32(&g_degT[c], 1.0f);
    }
}

// ---------------------------------------------------------------------------
// Fused tf32 mma.sync GEMM:
//   out = gelu([aggA|aggT|h] @ [W|Wt|Ws]^T + deg*b + degT*bt + bs)
// CTA tile 128x128, K=384 as 12 chunks of 32. 8 warps: warpM = wid&3 (32 rows),
// warpN = wid>>2 (64 cols). Per warp: 2 m16 tiles x 8 n8 tiles.
// smem: sA[128][32], sB[128][32], tf32-converted, SW128-swizzled 128B rows.
// ---------------------------------------------------------------------------
#define SM_A    0
#define SM_B    16384
#define SM_BIAS 32768
#define SM_TOT  (32768 + 1536)

__global__ void __launch_bounds__(256, 2)
fused_gemm_kernel(const float* __restrict__ h,
                  const float* __restrict__ Ww, const float* __restrict__ Wtw,
                  const float* __restrict__ Wsw,
                  const float* __restrict__ b0, const float* __restrict__ b1,
                  const float* __restrict__ b2,
                  float* __restrict__ out, int Nn) {
    extern __shared__ char smem[];
    uint32_t sbase = smem_u32(smem);
    int tid  = threadIdx.x;
    int lane = tid & 31;
    int wid  = tid >> 5;
    int warpM = wid & 3;             // 0..3 -> row offset warpM*32
    int warpN = wid >> 2;            // 0..1 -> col offset warpN*64

    float* sbias = (float*)(smem + SM_BIAS);
    for (int i = tid; i < 384; i += 256)
        sbias[i] = (i < 128) ? b0[i] : (i < 256) ? b1[i - 128] : b2[i - 256];

    int m0 = blockIdx.x * 128;

    float acc[2][8][4];
    #pragma unroll
    for (int mt = 0; mt < 2; mt++)
        #pragma unroll
        for (int nt = 0; nt < 8; nt++)
            #pragma unroll
            for (int q = 0; q < 4; q++) acc[mt][nt][q] = 0.f;

    // ldmatrix base addresses (per-thread row pointers), reused every chunk.
    // A-frag (x4): g = lane>>3: {m0k0, m8k0, m0k4, m8k4}
    int ag = lane >> 3, ar = lane & 7;
    // B-frag (x4): {n0k0, n0k4, n8k0, n8k4}
    int bg = lane >> 3, br = lane & 7;

    for (int s = 0; s < 12; s++) {
        int src = s >> 2;
        int chk = s & 3;
        const float* A = (src == 0) ? g_aggA : (src == 1) ? g_aggT : h;
        const float* B = (src == 0) ? Ww     : (src == 1) ? Wtw    : Wsw;

        __syncthreads();
        // Global -> smem (tf32-converted at load). 1024 float4 slots each.
        #pragma unroll
        for (int i = 0; i < 4; i++) {
            int idx = tid + i * 256;
            int row = idx >> 3;
            int c16 = idx & 7;
            uint32_t off = (uint32_t)(row * 128 + c16 * 16);
            uint32_t sw  = SWZ(off);
            int m = m0 + row;
            float4 av = (m < Nn)
                ? *(const float4*)(A + (size_t)m * DFEAT + chk * 32 + c16 * 4)
                : make_float4(0.f, 0.f, 0.f, 0.f);
            uint4 at = make_uint4(f32_to_tf32(av.x), f32_to_tf32(av.y),
                                  f32_to_tf32(av.z), f32_to_tf32(av.w));
            *(uint4*)(smem + SM_A + sw) = at;
            float4 bv = *(const float4*)(B + (size_t)row * DFEAT + chk * 32 + c16 * 4);
            uint4 bt = make_uint4(f32_to_tf32(bv.x), f32_to_tf32(bv.y),
                                  f32_to_tf32(bv.z), f32_to_tf32(bv.w));
            *(uint4*)(smem + SM_B + sw) = bt;
        }
        __syncthreads();

        #pragma unroll
        for (int k8 = 0; k8 < 4; k8++) {
            int k0b = k8 * 32;                       // byte offset of k0 within row
            uint32_t a[2][4];
            #pragma unroll
            for (int mt = 0; mt < 2; mt++) {
                int row = warpM * 32 + mt * 16 + (ag & 1) * 8 + ar;
                uint32_t off = (uint32_t)(row * 128 + k0b + (ag >> 1) * 16);
                ldsm_x4(a[mt][0], a[mt][1], a[mt][2], a[mt][3],
                        sbase + SM_A + SWZ(off));
            }
            uint32_t b[4][4];
            #pragma unroll
            for (int np = 0; np < 4; np++) {
                int row = warpN * 64 + np * 16 + (bg >> 1) * 8 + br;
                uint32_t off = (uint32_t)(row * 128 + k0b + (bg & 1) * 16);
                ldsm_x4(b[np][0], b[np][1], b[np][2], b[np][3],
                        sbase + SM_B + SWZ(off));
            }
            #pragma unroll
            for (int mt = 0; mt < 2; mt++)
                #pragma unroll
                for (int np = 0; np < 4; np++) {
                    mma_tf32(acc[mt][2 * np + 0], a[mt], &b[np][0]);
                    mma_tf32(acc[mt][2 * np + 1], a[mt], &b[np][2]);
                }
        }
    }

    // Epilogue: bias + degree-scaled biases + exact GELU, float2 stores
    const float inv_sqrt2 = 0.70710678118654752440f;
    #pragma unroll
    for (int mt = 0; mt < 2; mt++) {
        #pragma unroll
        for (int half = 0; half < 2; half++) {       // c0c1 vs c2c3 (row, row+8)
            int m = m0 + warpM * 32 + mt * 16 + half * 8 + (lane >> 2);
            if (m >= Nn) continue;
            float dg  = g_deg[m];
            float dgt = g_degT[m];
            #pragma unroll
            for (int nt = 0; nt < 8; nt++) {
                int n = warpN * 64 + nt * 8 + (lane & 3) * 2;
                float x0 = acc[mt][nt][half * 2 + 0]
                         + dg * sbias[n] + dgt * sbias[128 + n] + sbias[256 + n];
                float x1 = acc[mt][nt][half * 2 + 1]
                         + dg * sbias[n + 1] + dgt * sbias[128 + n + 1] + sbias[256 + n + 1];
                float2 v;
                v.x = 0.5f * x0 * (1.0f + erff(x0 * inv_sqrt2));
                v.y = 0.5f * x1 * (1.0f + erff(x1 * inv_sqrt2));
                *(float2*)(out + (size_t)m * DFEAT + n) = v;
            }
        }
    }
}

// ---------------------------------------------------------------------------
extern "C" void kernel_launch(void* const* d_in, const int* in_sizes, int n_in,
                              void* d_out, int out_size) {
    const float* h    = (const float*)d_in[0];
    const float* W_w  = (const float*)d_in[1];
    const float* W_b  = (const float*)d_in[2];
    const float* Wt_w = (const float*)d_in[3];
    const float* Wt_b = (const float*)d_in[4];
    const float* Ws_w = (const float*)d_in[5];
    const float* Ws_b = (const float*)d_in[6];
    const int*   rows = (const int*)d_in[7];
    const int*   cols = (const int*)d_in[8];
    int Nn = in_sizes[0] / DFEAT;
    int E  = in_sizes[7];
    float* out = (float*)d_out;

    // 1. zero accumulators + degree counters
    int n4each = Nn * DFEAT / 4;
    int nd4 = (Nn + 3) / 4;
    int ztot = 2 * n4each + 2 * nd4;
    zero_kernel<<<(ztot + 255) / 256, 256>>>(n4each, nd4);

    // 2. edge aggregation in h-space
    int eblocks = (E + 7) / 8;           // 8 warps (edges) per 256-thr block
    edge_kernel<<<eblocks, 256>>>(rows, cols, h, E);

    // 3. fused tf32 GEMM + bias + degree-bias + GELU
    fused_gemm_kernel<<<(Nn + 127) / 128, 256, SM_TOT>>>(
        h, W_w, Wt_w, Ws_w, W_b, Wt_b, Ws_b, out, Nn);
}

// round 10
// speedup vs baseline: 4.9713x; 1.8939x over previous
#include <cuda_runtime.h>
#include <cstdint>
#include <math.h>

#define NNODES 100000
#define NPAD   (NNODES + 128)
#define DFEAT  128
#define EMAX   1700000

// ---------------------------------------------------------------------------
// Scratch (allocation-free device globals; zero-initialized at module load)
// ---------------------------------------------------------------------------
__device__ float g_aggA[NPAD * DFEAT];     // tf32-rounded (A  h)
__device__ float g_aggT[NPAD * DFEAT];     // tf32-rounded (A^T h)
__device__ float g_hc  [NPAD * DFEAT];     // tf32-rounded h
__device__ float g_Wc  [3 * DFEAT * DFEAT];// tf32-rounded [W|Wt|Ws]
__device__ int g_degi [NNODES + 32];
__device__ int g_degiT[NNODES + 32];
__device__ int g_start [NNODES + 32];
__device__ int g_startT[NNODES + 32];
__device__ int g_cur [NNODES + 32];
__device__ int g_curT[NNODES + 32];
__device__ int g_csr[EMAX];                // neighbor (col) per out-edge bucket
__device__ int g_csc[EMAX];                // neighbor (row) per in-edge bucket
__device__ int g_bsum[2][512];

// ---------------------------------------------------------------------------
// PTX helpers (base-target only)
// ---------------------------------------------------------------------------
__device__ __forceinline__ uint32_t smem_u32(const void* p) {
    uint32_t a;
    asm("{ .reg .u64 t; cvta.to.shared.u64 t, %1; cvt.u32.u64 %0, t; }"
        : "=r"(a) : "l"(p));
    return a;
}
__device__ __forceinline__ uint32_t f32_to_tf32(float f) {
    uint32_t r;
    asm("cvt.rna.tf32.f32 %0, %1;" : "=r"(r) : "f"(f));
    return r;
}
__device__ __forceinline__ void ldsm_x4(uint32_t& r0, uint32_t& r1,
                                        uint32_t& r2, uint32_t& r3,
                                        uint32_t addr) {
    asm volatile("ldmatrix.sync.aligned.m8n8.x4.shared.b16 {%0,%1,%2,%3}, [%4];"
                 : "=r"(r0), "=r"(r1), "=r"(r2), "=r"(r3) : "r"(addr));
}
__device__ __forceinline__ void mma_tf32(float* d, const uint32_t* a,
                                         const uint32_t* b) {
    asm volatile(
        "mma.sync.aligned.m16n8k8.row.col.f32.tf32.tf32.f32 "
        "{%0,%1,%2,%3}, {%4,%5,%6,%7}, {%8,%9}, {%0,%1,%2,%3};"
        : "+f"(d[0]), "+f"(d[1]), "+f"(d[2]), "+f"(d[3])
        : "r"(a[0]), "r"(a[1]), "r"(a[2]), "r"(a[3]), "r"(b[0]), "r"(b[1]));
}
__device__ __forceinline__ void cp16(uint32_t dst, const void* src) {
    asm volatile("cp.async.ca.shared.global [%0], [%1], 16;"
                 :: "r"(dst), "l"(src) : "memory");
}
#define CP_COMMIT() asm volatile("cp.async.commit_group;" ::: "memory")
#define CP_WAIT1()  asm volatile("cp.async.wait_group 1;" ::: "memory")
#define CP_WAIT0()  asm volatile("cp.async.wait_group 0;" ::: "memory")
#define SWZ(off) ((off) ^ (((off) >> 3) & 0x70))

// ---------------------------------------------------------------------------
// Prep kernels
// ---------------------------------------------------------------------------
__global__ void zero_deg_kernel(int Nn) {
    int i = blockIdx.x * blockDim.x + threadIdx.x;
    if (i < Nn) { g_degi[i] = 0; g_degiT[i] = 0; }
}

__global__ void hist_kernel(const int* __restrict__ rows,
                            const int* __restrict__ cols, int E) {
    int e = blockIdx.x * blockDim.x + threadIdx.x;
    if (e >= E) return;
    atomicAdd(&g_degi [rows[e]], 1);
    atomicAdd(&g_degiT[cols[e]], 1);
}

__global__ void scan1_kernel(int Nn) {
    int arr = blockIdx.y;
    const int* deg = arr ? g_degiT : g_degi;
    int* startp    = arr ? g_startT : g_start;
    __shared__ int sm[256];
    int i = blockIdx.x * 256 + threadIdx.x;
    int v = (i < Nn) ? deg[i] : 0;
    sm[threadIdx.x] = v;
    __syncthreads();
    #pragma unroll
    for (int o = 1; o < 256; o <<= 1) {
        int t = (threadIdx.x >= o) ? sm[threadIdx.x - o] : 0;
        __syncthreads();
        sm[threadIdx.x] += t;
        __syncthreads();
    }
    if (i < Nn) startp[i] = sm[threadIdx.x] - v;  // exclusive within block
    if (threadIdx.x == 255) g_bsum[arr][blockIdx.x] = sm[255];
}

__global__ void scan2_kernel(int nb) {
    int arr = blockIdx.y;
    __shared__ int sm[512];
    int t = threadIdx.x;
    int v = (t < nb) ? g_bsum[arr][t] : 0;
    sm[t] = v;
    __syncthreads();
    #pragma unroll
    for (int o = 1; o < 512; o <<= 1) {
        int u = (t >= o) ? sm[t - o] : 0;
        __syncthreads();
        sm[t] += u;
        __syncthreads();
    }
    if (t < nb) g_bsum[arr][t] = sm[t] - v;       // exclusive
}

__global__ void scan3_kernel(int Nn) {
    int arr = blockIdx.y;
    int* startp = arr ? g_startT : g_start;
    int* curp   = arr ? g_curT   : g_cur;
    int i = blockIdx.x * 256 + threadIdx.x;
    if (i >= Nn) return;
    int s = startp[i] + g_bsum[arr][blockIdx.x];
    startp[i] = s;
    curp[i]   = s;
}

__global__ void scatter_kernel(const int* __restrict__ rows,
                               const int* __restrict__ cols, int E) {
    int e = blockIdx.x * blockDim.x + threadIdx.x;
    if (e >= E) return;
    int r = rows[e], c = cols[e];
    int p  = atomicAdd(&g_cur [r], 1);
    g_csr[p]  = c;
    int p2 = atomicAdd(&g_curT[c], 1);
    g_csc[p2] = r;
}

__global__ void convert_h_kernel(const float* __restrict__ h, int n4) {
    int i = blockIdx.x * blockDim.x + threadIdx.x;
    if (i >= n4) return;
    float4 v = ((const float4*)h)[i];
    uint4 o = make_uint4(f32_to_tf32(v.x), f32_to_tf32(v.y),
                         f32_to_tf32(v.z), f32_to_tf32(v.w));
    ((uint4*)g_hc)[i] = o;
}

__global__ void convert_W_kernel(const float* __restrict__ W0,
                                 const float* __restrict__ W1,
                                 const float* __restrict__ W2) {
    int i = blockIdx.x * blockDim.x + threadIdx.x;   // 0..12287 float4
    const float* src = (i < 4096) ? W0 : (i < 8192) ? W1 : W2;
    int j = i & 4095;
    float4 v = ((const float4*)src)[j];
    uint4 o = make_uint4(f32_to_tf32(v.x), f32_to_tf32(v.y),
                         f32_to_tf32(v.z), f32_to_tf32(v.w));
    ((uint4*)g_Wc)[i] = o;
}

// ---------------------------------------------------------------------------
// Gather aggregation: one warp per (node, direction). No float atomics.
//   dir 0: aggA[i] = sum_{e: rows=i} h[cols[e]]     (list g_csr)
//   dir 1: aggT[i] = sum_{e: cols=i} h[rows[e]]     (list g_csc)
// Output rows stored tf32-rounded (exact operands for the tf32 GEMM).
// ---------------------------------------------------------------------------
__global__ void __launch_bounds__(256)
aggregate_kernel(const float* __restrict__ h, int Nn) {
    int dir  = blockIdx.y;
    int node = blockIdx.x * 8 + (threadIdx.x >> 5);
    int lane = threadIdx.x & 31;
    if (node >= Nn) return;
    const int* startp = dir ? g_startT : g_start;
    const int* degp   = dir ? g_degiT  : g_degi;
    const int* lst    = dir ? g_csc    : g_csr;
    float* outp       = dir ? g_aggT   : g_aggA;

    int s0 = startp[node];
    int n  = degp[node];

    float4 acc = make_float4(0.f, 0.f, 0.f, 0.f);
    int t = 0;
    for (; t + 4 <= n; t += 4) {
        int j0 = lst[s0 + t + 0];
        int j1 = lst[s0 + t + 1];
        int j2 = lst[s0 + t + 2];
        int j3 = lst[s0 + t + 3];
        float4 v0 = __ldg((const float4*)(h + (size_t)j0 * DFEAT + lane * 4));
        float4 v1 = __ldg((const float4*)(h + (size_t)j1 * DFEAT + lane * 4));
        float4 v2 = __ldg((const float4*)(h + (size_t)j2 * DFEAT + lane * 4));
        float4 v3 = __ldg((const float4*)(h + (size_t)j3 * DFEAT + lane * 4));
        acc.x += v0.x + v1.x + v2.x + v3.x;
        acc.y += v0.y + v1.y + v2.y + v3.y;
        acc.z += v0.z + v1.z + v2.z + v3.z;
        acc.w += v0.w + v1.w + v2.w + v3.w;
    }
    for (; t < n; t++) {
        int j = lst[s0 + t];
        float4 v = __ldg((const float4*)(h + (size_t)j * DFEAT + lane * 4));
        acc.x += v.x; acc.y += v.y; acc.z += v.z; acc.w += v.w;
    }
    uint4 o = make_uint4(f32_to_tf32(acc.x), f32_to_tf32(acc.y),
                         f32_to_tf32(acc.z), f32_to_tf32(acc.w));
    *(uint4*)(outp + (size_t)node * DFEAT + lane * 4) = o;
}

// ---------------------------------------------------------------------------
// Fused tf32 mma.sync GEMM, cp.async double-buffered:
//   out = gelu([aggA|aggT|hc] @ Wc^T + deg*b + degT*bt + bs)
// All GEMM inputs are pre-rounded tf32 bits -> copy raw, no cvt in the loop.
// ---------------------------------------------------------------------------
#define SM_BUF(b)  ((b) * 32768)          // each buf: A 16KB + B 16KB
#define SM_BIAS    65536
#define SM_TOT     (65536 + 1536)

__global__ void __launch_bounds__(256, 2)
fused_gemm_kernel(const float* __restrict__ b0, const float* __restrict__ b1,
                  const float* __restrict__ b2,
                  float* __restrict__ out, int Nn) {
    extern __shared__ char smem[];
    uint32_t sbase = smem_u32(smem);
    int tid  = threadIdx.x;
    int lane = tid & 31;
    int wid  = tid >> 5;
    int warpM = wid & 3;
    int warpN = wid >> 2;
    int m0 = blockIdx.x * 128;

    float* sbias = (float*)(smem + SM_BIAS);
    for (int i = tid; i < 384; i += 256)
        sbias[i] = (i < 128) ? b0[i] : (i < 256) ? b1[i - 128] : b2[i - 256];

    // --- cp.async issue for chunk s into buffer b ---
    auto issue = [&](int s, int b) {
        int src = s >> 2, chk = s & 3;
        const float* A = (src == 0) ? g_aggA : (src == 1) ? g_aggT : g_hc;
        const float* B = g_Wc + src * (DFEAT * DFEAT);
        uint32_t a_off = SM_BUF(b), b_off = SM_BUF(b) + 16384;
        #pragma unroll
        for (int i = 0; i < 4; i++) {
            int idx = tid + i * 256;          // 0..1023
            int row = idx >> 3;
            int c16 = idx & 7;
            uint32_t sw = SWZ((uint32_t)(row * 128 + c16 * 16));
            cp16(sbase + a_off + sw,
                 A + (size_t)(m0 + row) * DFEAT + chk * 32 + c16 * 4);
            cp16(sbase + b_off + sw,
                 B + (size_t)row * DFEAT + chk * 32 + c16 * 4);
        }
        CP_COMMIT();
    };

    float acc[2][8][4];
    #pragma unroll
    for (int mt = 0; mt < 2; mt++)
        #pragma unroll
        for (int nt = 0; nt < 8; nt++)
            #pragma unroll
            for (int q = 0; q < 4; q++) acc[mt][nt][q] = 0.f;

    int ag = lane >> 3, ar = lane & 7;
    int bg = lane >> 3, br = lane & 7;

    issue(0, 0);
    for (int s = 0; s < 12; s++) {
        int buf = s & 1;
        if (s < 11) { issue(s + 1, buf ^ 1); CP_WAIT1(); }
        else        { CP_WAIT0(); }
        __syncthreads();

        uint32_t a_off = SM_BUF(buf), b_off = SM_BUF(buf) + 16384;
        #pragma unroll
        for (int k8 = 0; k8 < 4; k8++) {
            int k0b = k8 * 32;
            uint32_t a[2][4];
            #pragma unroll
            for (int mt = 0; mt < 2; mt++) {
                int row = warpM * 32 + mt * 16 + (ag & 1) * 8 + ar;
                uint32_t off = (uint32_t)(row * 128 + k0b + (ag >> 1) * 16);
                ldsm_x4(a[mt][0], a[mt][1], a[mt][2], a[mt][3],
                        sbase + a_off + SWZ(off));
            }
            uint32_t b[4][4];
            #pragma unroll
            for (int np = 0; np < 4; np++) {
                int row = warpN * 64 + np * 16 + (bg >> 1) * 8 + br;
                uint32_t off = (uint32_t)(row * 128 + k0b + (bg & 1) * 16);
                ldsm_x4(b[np][0], b[np][1], b[np][2], b[np][3],
                        sbase + b_off + SWZ(off));
            }
            #pragma unroll
            for (int mt = 0; mt < 2; mt++)
                #pragma unroll
                for (int np = 0; np < 4; np++) {
                    mma_tf32(acc[mt][2 * np + 0], a[mt], &b[np][0]);
                    mma_tf32(acc[mt][2 * np + 1], a[mt], &b[np][2]);
                }
        }
        __syncthreads();
    }

    // Epilogue: bias + degree-scaled biases + exact GELU
    const float inv_sqrt2 = 0.70710678118654752440f;
    #pragma unroll
    for (int mt = 0; mt < 2; mt++) {
        #pragma unroll
        for (int half = 0; half < 2; half++) {
            int m = m0 + warpM * 32 + mt * 16 + half * 8 + (lane >> 2);
            if (m >= Nn) continue;
            float dg  = (float)__ldg(&g_degi [m]);
            float dgt = (float)__ldg(&g_degiT[m]);
            #pragma unroll
            for (int nt = 0; nt < 8; nt++) {
                int n = warpN * 64 + nt * 8 + (lane & 3) * 2;
                float x0 = acc[mt][nt][half * 2 + 0]
                         + dg * sbias[n] + dgt * sbias[128 + n] + sbias[256 + n];
                float x1 = acc[mt][nt][half * 2 + 1]
                         + dg * sbias[n + 1] + dgt * sbias[128 + n + 1]
                         + sbias[256 + n + 1];
                float2 v;
                v.x = 0.5f * x0 * (1.0f + erff(x0 * inv_sqrt2));
                v.y = 0.5f * x1 * (1.0f + erff(x1 * inv_sqrt2));
                *(float2*)(out + (size_t)m * DFEAT + n) = v;
            }
        }
    }
}

// ---------------------------------------------------------------------------
extern "C" void kernel_launch(void* const* d_in, const int* in_sizes, int n_in,
                              void* d_out, int out_size) {
    const float* h    = (const float*)d_in[0];
    const float* W_w  = (const float*)d_in[1];
    const float* W_b  = (const float*)d_in[2];
    const float* Wt_w = (const float*)d_in[3];
    const float* Wt_b = (const float*)d_in[4];
    const float* Ws_w = (const float*)d_in[5];
    const float* Ws_b = (const float*)d_in[6];
    const int*   rows = (const int*)d_in[7];
    const int*   cols = (const int*)d_in[8];
    int Nn = in_sizes[0] / DFEAT;
    int E  = in_sizes[7];
    float* out = (float*)d_out;

    int nblk256 = (Nn + 255) / 256;

    // 1. CSR/CSC build
    zero_deg_kernel<<<nblk256, 256>>>(Nn);
    hist_kernel<<<(E + 255) / 256, 256>>>(rows, cols, E);
    scan1_kernel<<<dim3(nblk256, 2), 256>>>(Nn);
    scan2_kernel<<<dim3(1, 2), 512>>>(nblk256);
    scan3_kernel<<<dim3(nblk256, 2), 256>>>(Nn);
    scatter_kernel<<<(E + 255) / 256, 256>>>(rows, cols, E);

    // 2. tf32 conversions (independent of CSR build)
    int n4 = Nn * DFEAT / 4;
    convert_h_kernel<<<(n4 + 255) / 256, 256>>>(h, n4);
    convert_W_kernel<<<48, 256>>>(W_w, Wt_w, Ws_w);

    // 3. Gather aggregation (no float atomics)
    aggregate_kernel<<<dim3((Nn + 7) / 8, 2), 256>>>(h, Nn);

    // 4. Fused cp.async tf32 GEMM + degree-bias + GELU
    cudaFuncSetAttribute(fused_gemm_kernel,
                         cudaFuncAttributeMaxDynamicSharedMemorySize, SM_TOT);
    fused_gemm_kernel<<<(Nn + 127) / 128, 256, SM_TOT>>>(
        W_b, Wt_b, Ws_b, out, Nn);
}